// round 1
// baseline (speedup 1.0000x reference)
#include <cuda_runtime.h>
#include <math.h>

// Problem constants
#define B_      4
#define NQ      2048
#define NK      1024
#define DQ      512
#define DC      768
#define HEADS   8
#define DIMH    64
#define INNER   512           // HEADS*DIMH
#define SCALE   0.125f        // 1/sqrt(64)

// -------- device scratch (no allocations allowed) --------
__device__ float g_q [B_ * NQ * INNER];   // 16 MB
__device__ float g_k [B_ * NK * INNER];   // 8 MB
__device__ float g_v [B_ * NK * INNER];   // 8 MB
__device__ float g_ao[B_ * NQ * INNER];   // 16 MB

// ============================================================
// Generic tiled SGEMM: C[M,N] = A[M,K] @ B[K,N] (+ bias[N])
// BM=BN=64, BK=16, 256 threads, 4x4 per thread.
// M,N,K all multiples of 64/16 for this problem -> no guards.
// ============================================================
__global__ __launch_bounds__(256)
void sgemm_kernel(const float* __restrict__ A, const float* __restrict__ Bm,
                  float* __restrict__ C, int M, int N, int K,
                  const float* __restrict__ bias)
{
    __shared__ float As[16][64];   // transposed A tile: As[k][m]
    __shared__ float Bs[16][64];   // Bs[k][n]

    const int tid = threadIdx.x;
    const int tx  = tid & 15;          // 0..15 -> n
    const int ty  = tid >> 4;          // 0..15 -> m
    const int bm  = blockIdx.y * 64;
    const int bn  = blockIdx.x * 64;

    float acc[4][4];
#pragma unroll
    for (int i = 0; i < 4; i++)
#pragma unroll
        for (int j = 0; j < 4; j++) acc[i][j] = 0.f;

    const int nKt = K >> 4;
    // A-load mapping: row = tid/4 (0..63), kcol0 = (tid%4)*4
    const int ar  = tid >> 2;
    const int ac0 = (tid & 3) * 4;
    // B-load mapping: krow = tid/16, ncol0 = (tid%16)*4
    const int br  = tid >> 4;
    const int bc0 = (tid & 15) * 4;

    for (int kt = 0; kt < nKt; kt++) {
        // load A tile (64 x 16), store transposed
        {
            const float4 av = *reinterpret_cast<const float4*>(
                &A[(size_t)(bm + ar) * K + kt * 16 + ac0]);
            As[ac0 + 0][ar] = av.x;
            As[ac0 + 1][ar] = av.y;
            As[ac0 + 2][ar] = av.z;
            As[ac0 + 3][ar] = av.w;
        }
        // load B tile (16 x 64)
        {
            const float4 bv = *reinterpret_cast<const float4*>(
                &Bm[(size_t)(kt * 16 + br) * N + bn + bc0]);
            *reinterpret_cast<float4*>(&Bs[br][bc0]) = bv;
        }
        __syncthreads();

#pragma unroll
        for (int k = 0; k < 16; k++) {
            float a0 = As[k][ty * 4 + 0];
            float a1 = As[k][ty * 4 + 1];
            float a2 = As[k][ty * 4 + 2];
            float a3 = As[k][ty * 4 + 3];
            float4 bv = *reinterpret_cast<const float4*>(&Bs[k][tx * 4]);
            acc[0][0] += a0 * bv.x; acc[0][1] += a0 * bv.y; acc[0][2] += a0 * bv.z; acc[0][3] += a0 * bv.w;
            acc[1][0] += a1 * bv.x; acc[1][1] += a1 * bv.y; acc[1][2] += a1 * bv.z; acc[1][3] += a1 * bv.w;
            acc[2][0] += a2 * bv.x; acc[2][1] += a2 * bv.y; acc[2][2] += a2 * bv.z; acc[2][3] += a2 * bv.w;
            acc[3][0] += a3 * bv.x; acc[3][1] += a3 * bv.y; acc[3][2] += a3 * bv.z; acc[3][3] += a3 * bv.w;
        }
        __syncthreads();
    }

#pragma unroll
    for (int i = 0; i < 4; i++) {
        const int row = bm + ty * 4 + i;
        const int col = bn + tx * 4;
        float4 out;
        out.x = acc[i][0]; out.y = acc[i][1]; out.z = acc[i][2]; out.w = acc[i][3];
        if (bias) {
            out.x += bias[col + 0];
            out.y += bias[col + 1];
            out.z += bias[col + 2];
            out.w += bias[col + 3];
        }
        *reinterpret_cast<float4*>(&C[(size_t)row * N + col]) = out;
    }
}

// ============================================================
// Flash attention (fp32): one thread owns one query row.
// Block = 128 threads = 128 query rows for one (b,h).
// K/V staged in shared as 32-key tiles of float4[16] (d=64).
// ============================================================
__global__ __launch_bounds__(128)
void attn_kernel(const float* __restrict__ q, const float* __restrict__ k,
                 const float* __restrict__ v, float* __restrict__ out)
{
    const int b   = blockIdx.z;
    const int h   = blockIdx.y;
    const int row = blockIdx.x * 128 + threadIdx.x;

    __shared__ float4 Ks[32][16];
    __shared__ float4 Vs[32][16];

    // load q row into registers
    float4 qr[16];
    {
        const float4* qp = reinterpret_cast<const float4*>(
            &q[((size_t)(b * NQ + row) * INNER) + h * DIMH]);
#pragma unroll
        for (int d = 0; d < 16; d++) qr[d] = qp[d];
    }

    float m = -INFINITY;
    float l = 0.f;
    float4 acc[16];
#pragma unroll
    for (int d = 0; d < 16; d++) acc[d] = make_float4(0.f, 0.f, 0.f, 0.f);

    const int nTiles = NK / 32;
    for (int kt = 0; kt < nTiles; kt++) {
        __syncthreads();
        // cooperative load of 32 keys + 32 values (512 float4 each)
#pragma unroll
        for (int t = 0; t < 4; t++) {
            const int e    = threadIdx.x + t * 128;   // 0..511
            const int jrow = e >> 4;
            const int d4   = e & 15;
            const size_t gk = ((size_t)(b * NK + kt * 32 + jrow) * INNER) + h * DIMH;
            Ks[jrow][d4] = reinterpret_cast<const float4*>(&k[gk])[d4];
            Vs[jrow][d4] = reinterpret_cast<const float4*>(&v[gk])[d4];
        }
        __syncthreads();

        // scores
        float s[32];
#pragma unroll
        for (int j = 0; j < 32; j++) {
            float acc_s = 0.f;
#pragma unroll
            for (int d = 0; d < 16; d++) {
                const float4 kk = Ks[j][d];
                acc_s += qr[d].x * kk.x + qr[d].y * kk.y
                       + qr[d].z * kk.z + qr[d].w * kk.w;
            }
            s[j] = acc_s * SCALE;
        }

        // online softmax
        float tmax = s[0];
#pragma unroll
        for (int j = 1; j < 32; j++) tmax = fmaxf(tmax, s[j]);
        const float m_new = fmaxf(m, tmax);
        const float corr  = __expf(m - m_new);
        l *= corr;
#pragma unroll
        for (int d = 0; d < 16; d++) {
            acc[d].x *= corr; acc[d].y *= corr;
            acc[d].z *= corr; acc[d].w *= corr;
        }
        m = m_new;

#pragma unroll
        for (int j = 0; j < 32; j++) {
            const float p = __expf(s[j] - m);
            l += p;
#pragma unroll
            for (int d = 0; d < 16; d++) {
                const float4 vv = Vs[j][d];
                acc[d].x += p * vv.x; acc[d].y += p * vv.y;
                acc[d].z += p * vv.z; acc[d].w += p * vv.w;
            }
        }
    }

    // write normalized output row
    const float inv = 1.f / l;
    float4* op = reinterpret_cast<float4*>(
        &out[((size_t)(b * NQ + row) * INNER) + h * DIMH]);
#pragma unroll
    for (int d = 0; d < 16; d++) {
        float4 o;
        o.x = acc[d].x * inv; o.y = acc[d].y * inv;
        o.z = acc[d].z * inv; o.w = acc[d].w * inv;
        op[d] = o;
    }
}

// ============================================================
extern "C" void kernel_launch(void* const* d_in, const int* in_sizes, int n_in,
                              void* d_out, int out_size)
{
    const float* x   = (const float*)d_in[0];   // [4,2048,512]
    const float* ctx = (const float*)d_in[1];   // [4,1024,768]
    const float* Wq  = (const float*)d_in[2];   // [512,512]
    const float* Wk  = (const float*)d_in[3];   // [768,512]
    const float* Wv  = (const float*)d_in[4];   // [768,512]
    const float* Wo  = (const float*)d_in[5];   // [512,512]
    const float* bo  = (const float*)d_in[6];   // [512]
    float* out       = (float*)d_out;           // [4,2048,512]

    float *q, *k, *v, *ao;
    cudaGetSymbolAddress((void**)&q,  g_q);
    cudaGetSymbolAddress((void**)&k,  g_k);
    cudaGetSymbolAddress((void**)&v,  g_v);
    cudaGetSymbolAddress((void**)&ao, g_ao);

    // Q = x @ Wq : [8192,512] = [8192,512]@[512,512]
    {
        dim3 grid(INNER / 64, (B_ * NQ) / 64);
        sgemm_kernel<<<grid, 256>>>(x, Wq, q, B_ * NQ, INNER, DQ, nullptr);
    }
    // K = ctx @ Wk : [4096,512] = [4096,768]@[768,512]
    {
        dim3 grid(INNER / 64, (B_ * NK) / 64);
        sgemm_kernel<<<grid, 256>>>(ctx, Wk, k, B_ * NK, INNER, DC, nullptr);
    }
    // V = ctx @ Wv
    {
        dim3 grid(INNER / 64, (B_ * NK) / 64);
        sgemm_kernel<<<grid, 256>>>(ctx, Wv, v, B_ * NK, INNER, DC, nullptr);
    }
    // attention
    {
        dim3 grid(NQ / 128, HEADS, B_);
        attn_kernel<<<grid, 128>>>(q, k, v, ao);
    }
    // out = ao @ Wo + bo
    {
        dim3 grid(DQ / 64, (B_ * NQ) / 64);
        sgemm_kernel<<<grid, 256>>>(ao, Wo, out, B_ * NQ, DQ, INNER, bo);
    }
}